// round 10
// baseline (speedup 1.0000x reference)
#include <cuda_runtime.h>
#include <cuda_fp16.h>

// R10: uniform-address gather experiment.
// Same quad table + sector count as R9, but gathers issued as warp-uniform
// LDGs (one per point, broadcast wavefront) instead of one divergent LDG per
// 32 points (which replays at 2.07 cyc/wavefront per B300 microarch data).
//   d_in[0] = points [N,2] fp32, d_in[1] = grid [1024,1024] fp32,
//   d_in[2] = bounds [2,2] fp32, d_out = [N] fp32

#define GRID_W 1024
#define GRID_H 1024
#define QUAD_STRIDE 1024
#define QUAD_ROWS   (GRID_H - 1)

__device__ uint2 g_quad[QUAD_ROWS * QUAD_STRIDE];

__global__ __launch_bounds__(256)
void build_quad_kernel(const float* __restrict__ grid) {
    int t = blockIdx.x * blockDim.x + threadIdx.x;
    if (t >= QUAD_ROWS * (GRID_W / 4)) return;
    int y  = t >> 8;
    int xb = (t & 255) << 2;

    const float* r0 = grid + (y << 10) + xb;
    const float* r1 = r0 + GRID_W;

    float4 a0 = *reinterpret_cast<const float4*>(r0);
    float4 a1 = *reinterpret_cast<const float4*>(r1);
    int noff = (xb == GRID_W - 4) ? 3 : 4;   // quad at x=1023 never gathered
    float e0 = r0[noff];
    float e1 = r1[noff];

    float t0[5] = {a0.x, a0.y, a0.z, a0.w, e0};
    float b0[5] = {a1.x, a1.y, a1.z, a1.w, e1};

    uint2 q[4];
#pragma unroll
    for (int k = 0; k < 4; k++) {
        __half2 top = __floats2half2_rn(t0[k], t0[k + 1]);
        __half2 bot = __floats2half2_rn(b0[k], b0[k + 1]);
        q[k].x = *reinterpret_cast<unsigned int*>(&top);
        q[k].y = *reinterpret_cast<unsigned int*>(&bot);
    }

    uint2* dst = &g_quad[(y << 10) + xb];
    reinterpret_cast<uint4*>(dst)[0] = make_uint4(q[0].x, q[0].y, q[1].x, q[1].y);
    reinterpret_cast<uint4*>(dst)[1] = make_uint4(q[2].x, q[2].y, q[3].x, q[3].y);
}

__global__ __launch_bounds__(128, 16)
void tableInterp_kernel(const float4* __restrict__ pts,
                        const float* __restrict__ bounds,
                        float* __restrict__ out,
                        int n_quads) {   // groups of 4 points; grid sized exactly
    int i = blockIdx.x * blockDim.x + threadIdx.x;
    int lane = threadIdx.x & 31;

    float x_lo = __ldg(bounds + 0);
    float x_hi = __ldg(bounds + 1);
    float v_lo = __ldg(bounds + 2);
    float v_hi = __ldg(bounds + 3);
    float sy = (float)(GRID_H - 1) / (x_hi - x_lo);
    float sx = (float)(GRID_W - 1) / (v_hi - v_lo);

    float4 p01 = __ldcs(&pts[2 * i]);
    float4 p23 = __ldcs(&pts[2 * i + 1]);

    float px[4] = {p01.x, p01.z, p23.x, p23.z};
    float pv[4] = {p01.y, p01.w, p23.y, p23.w};

    // Phase 1: per-lane index + alpha computation (parallel).
    int   idx[4];
    float ax[4], ay[4];
#pragma unroll
    for (int k = 0; k < 4; k++) {
        float qy = (px[k] - x_lo) * sy;
        float qx = (pv[k] - v_lo) * sx;
        float fy = fminf(fmaxf(floorf(qy), 0.0f), (float)(GRID_H - 2));
        float fx = fminf(fmaxf(floorf(qx), 0.0f), (float)(GRID_W - 2));
        ay[k] = fminf(fmaxf(qy - fy, 0.0f), 1.0f);
        ax[k] = fminf(fmaxf(qx - fx, 0.0f), 1.0f);
        idx[k] = (((int)fy) << 10) + (int)fx;
    }

    // Phase 2: uniform-address gathers. For each source lane j, broadcast its
    // 4 indices; ALL lanes issue the same-address LDG (single broadcast
    // wavefront, no divergent replay); owning lane keeps the result.
    uint2 myq[4];
#pragma unroll
    for (int j = 0; j < 32; j++) {
        bool own = (lane == j);
#pragma unroll
        for (int k = 0; k < 4; k++) {
            int uidx = __shfl_sync(0xffffffffu, idx[k], j);
            uint2 q = __ldg(&g_quad[uidx]);
            if (own) myq[k] = q;
        }
    }

    // Phase 3: blend + streaming store.
    float r[4];
#pragma unroll
    for (int k = 0; k < 4; k++) {
        float2 t = __half22float2(*reinterpret_cast<const __half2*>(&myq[k].x));
        float2 b = __half22float2(*reinterpret_cast<const __half2*>(&myq[k].y));
        float top = fmaf(t.y - t.x, ax[k], t.x);
        float bot = fmaf(b.y - b.x, ax[k], b.x);
        r[k] = fmaf(bot - top, ay[k], top);
    }

    __stcs(reinterpret_cast<float4*>(out) + i, make_float4(r[0], r[1], r[2], r[3]));
}

extern "C" void kernel_launch(void* const* d_in, const int* in_sizes, int n_in,
                              void* d_out, int out_size) {
    const float4* pts  = (const float4*)d_in[0];
    const float*  grid = (const float*)d_in[1];
    const float*  bnds = (const float*)d_in[2];
    float*        out  = (float*)d_out;

    {
        int total = QUAD_ROWS * (GRID_W / 4);
        int threads = 256;
        int blocks = (total + threads - 1) / threads;
        build_quad_kernel<<<blocks, threads>>>(grid);
    }

    int n = in_sizes[0] / 2;   // number of points ([N,2])
    int n_quads = n / 4;       // 1048576; 128 | n_quads -> all warps full

    int threads = 128;
    int blocks = n_quads / threads;   // exact: 8192
    tableInterp_kernel<<<blocks, threads>>>(pts, bnds, out, n_quads);
}

// round 11
// speedup vs baseline: 2.1857x; 2.1857x over previous
#include <cuda_runtime.h>
#include <cuda_fp16.h>

// R11: R9 config + PDL overlap (build hidden behind main's streaming prologue).
//   d_in[0] = points [N,2] fp32, d_in[1] = grid [1024,1024] fp32,
//   d_in[2] = bounds [2,2] fp32, d_out = [N] fp32

#define GRID_W 1024
#define GRID_H 1024
#define QUAD_STRIDE 1024
#define QUAD_ROWS   (GRID_H - 1)

// quad[y*1024 + x] = half2(tl,tr), half2(bl,br) -> uint2, 8.4 MB
__device__ uint2 g_quad[QUAD_ROWS * QUAD_STRIDE];

__global__ __launch_bounds__(256)
void build_quad_kernel(const float* __restrict__ grid) {
    int t = blockIdx.x * blockDim.x + threadIdx.x;     // [0, 1023*256)
    if (t < QUAD_ROWS * (GRID_W / 4)) {
        int y  = t >> 8;            // row 0..1022
        int xb = (t & 255) << 2;    // x block start

        const float* r0 = grid + (y << 10) + xb;
        const float* r1 = r0 + GRID_W;

        float4 a0 = *reinterpret_cast<const float4*>(r0);
        float4 a1 = *reinterpret_cast<const float4*>(r1);
        int noff = (xb == GRID_W - 4) ? 3 : 4;   // quad at x=1023 never gathered
        float e0 = r0[noff];
        float e1 = r1[noff];

        float t0[5] = {a0.x, a0.y, a0.z, a0.w, e0};
        float b0[5] = {a1.x, a1.y, a1.z, a1.w, e1};

        uint2 q[4];
#pragma unroll
        for (int k = 0; k < 4; k++) {
            __half2 top = __floats2half2_rn(t0[k], t0[k + 1]);
            __half2 bot = __floats2half2_rn(b0[k], b0[k + 1]);
            q[k].x = *reinterpret_cast<unsigned int*>(&top);
            q[k].y = *reinterpret_cast<unsigned int*>(&bot);
        }

        uint2* dst = &g_quad[(y << 10) + xb];
        reinterpret_cast<uint4*>(dst)[0] = make_uint4(q[0].x, q[0].y, q[1].x, q[1].y);
        reinterpret_cast<uint4*>(dst)[1] = make_uint4(q[2].x, q[2].y, q[3].x, q[3].y);
    }
    // Signal dependents may proceed; all writes above are program-ordered
    // before the trigger, so they are visible after gridDependencySynchronize.
    cudaTriggerProgrammaticLaunchCompletion();
}

__global__ __launch_bounds__(128, 16)
void tableInterp_kernel(const float4* __restrict__ pts,
                        const float* __restrict__ bounds,
                        float* __restrict__ out,
                        int n_quads) {   // groups of 4 points
    int i = blockIdx.x * blockDim.x + threadIdx.x;
    if (i >= n_quads) {
        cudaGridDependencySynchronize();
        return;
    }

    float x_lo = __ldg(bounds + 0);
    float x_hi = __ldg(bounds + 1);
    float v_lo = __ldg(bounds + 2);
    float v_hi = __ldg(bounds + 3);
    float sy = (float)(GRID_H - 1) / (x_hi - x_lo);
    float sx = (float)(GRID_W - 1) / (v_hi - v_lo);

    // Streaming point loads — overlap with the build kernel (pre-sync phase).
    float4 p01 = __ldcs(&pts[2 * i]);
    float4 p23 = __ldcs(&pts[2 * i + 1]);

    float px[4] = {p01.x, p01.z, p23.x, p23.z};
    float pv[4] = {p01.y, p01.w, p23.y, p23.w};

    int   idx[4];
    float ax[4], ay[4];
#pragma unroll
    for (int k = 0; k < 4; k++) {
        float qy = (px[k] - x_lo) * sy;
        float qx = (pv[k] - v_lo) * sx;
        float fy = fminf(fmaxf(floorf(qy), 0.0f), (float)(GRID_H - 2));
        float fx = fminf(fmaxf(floorf(qx), 0.0f), (float)(GRID_W - 2));
        ay[k] = fminf(fmaxf(qy - fy, 0.0f), 1.0f);
        ax[k] = fminf(fmaxf(qx - fx, 0.0f), 1.0f);
        idx[k] = (((int)fy) << 10) + (int)fx;
    }

    // Wait for the build kernel's table writes, then gather.
    cudaGridDependencySynchronize();

    uint2 q[4];
#pragma unroll
    for (int k = 0; k < 4; k++) q[k] = __ldg(&g_quad[idx[k]]);

    float r[4];
#pragma unroll
    for (int k = 0; k < 4; k++) {
        float2 t = __half22float2(*reinterpret_cast<const __half2*>(&q[k].x)); // tl, tr
        float2 b = __half22float2(*reinterpret_cast<const __half2*>(&q[k].y)); // bl, br
        float top = fmaf(t.y - t.x, ax[k], t.x);
        float bot = fmaf(b.y - b.x, ax[k], b.x);
        r[k] = fmaf(bot - top, ay[k], top);
    }

    __stcs(reinterpret_cast<float4*>(out) + i, make_float4(r[0], r[1], r[2], r[3]));
}

extern "C" void kernel_launch(void* const* d_in, const int* in_sizes, int n_in,
                              void* d_out, int out_size) {
    const float4* pts  = (const float4*)d_in[0];
    const float*  grid = (const float*)d_in[1];
    const float*  bnds = (const float*)d_in[2];
    float*        out  = (float*)d_out;

    // Build kernel (primary).
    {
        int total = QUAD_ROWS * (GRID_W / 4);   // 1023 * 256
        int threads = 256;
        int blocks = (total + threads - 1) / threads;
        build_quad_kernel<<<blocks, threads>>>(grid);
    }

    int n = in_sizes[0] / 2;   // number of points ([N,2])
    int n_quads = n / 4;       // groups of 4 points

    // Main kernel (secondary) with programmatic dependent launch: may begin
    // while build is still running; gathers gated by gridDependencySynchronize.
    {
        cudaLaunchConfig_t cfg = {};
        cfg.gridDim  = dim3((n_quads + 127) / 128);
        cfg.blockDim = dim3(128);
        cfg.dynamicSmemBytes = 0;
        cfg.stream = 0;
        cudaLaunchAttribute attr[1];
        attr[0].id = cudaLaunchAttributeProgrammaticStreamSerialization;
        attr[0].val.programmaticStreamSerializationAllowed = 1;
        cfg.attrs = attr;
        cfg.numAttrs = 1;
        cudaLaunchKernelEx(&cfg, tableInterp_kernel, pts, bnds, out, n_quads);
    }
}